// round 1
// baseline (speedup 1.0000x reference)
#include <cuda_runtime.h>
#include <cuda_bf16.h>
#include <mma.h>

using namespace nvcuda;

// Problem constants: B=32, T=128, F=1024, CONV_UNITS=2048, SHORT_UNITS=2048, RATE=4
//   out[b, 0:2016,    :] = memory[b, 32:2048,   :]       (conv region shift)
//   out[b, 2016:2048, :] = compression[b, :, :]          (GEMM result)
//   out[b, 2048:3968, :] = memory[b, 2176:4096, :]       (short region shift)
//   out[b, 3968:4096, :] = inputs[b, :, :]
//
// compression[b,t,n] = sum_{w<4,k<1024} memory[b, 2048+4t+w, k] * conv_w[w,k,n] + conv_b[n]
// == A(1024x4096) @ W(4096x1024):
//   A row m=(b*32+t) = 4096 contiguous floats at memory + b*4194304 + 2097152 + t*4096
//   W = conv_w viewed as (4096, 1024) row-major.

// ---------------------------------------------------------------------------
// Copy kernel: pure shifted memcpy, float4-vectorized, grid-stride.
// ---------------------------------------------------------------------------
__global__ void copy_kernel(const float4* __restrict__ inputs,
                            const float4* __restrict__ memory,
                            float4* __restrict__ out)
{
    const unsigned total = 32u * 4096u * 256u;  // 33,554,432 float4
    const unsigned stride = gridDim.x * blockDim.x;
    for (unsigned v = blockIdx.x * blockDim.x + threadIdx.x; v < total; v += stride) {
        unsigned f4 = v & 255u;          // float4 index within row (F/4 = 256)
        unsigned rg = v >> 8;            // global row index b*4096 + r
        unsigned b  = rg >> 12;
        unsigned r  = rg & 4095u;
        float4 val;
        if (r < 2016u) {
            val = memory[(b << 20) + ((r + 32u) << 8) + f4];
        } else if (r < 2048u) {
            continue;  // compression band written by GEMM kernel
        } else if (r < 3968u) {
            val = memory[(b << 20) + ((r + 128u) << 8) + f4];
        } else {
            val = inputs[(b << 15) + ((r - 3968u) << 8) + f4];
        }
        out[v] = val;
    }
}

// ---------------------------------------------------------------------------
// TF32 WMMA GEMM: C(1024x1024) = A(1024x4096) @ W(4096x1024) + bias
// CTA tile 64x64, 4 warps (each 32x32), K staged 32 at a time.
// ---------------------------------------------------------------------------
#define TM 64
#define TN 64
#define TK 32

__global__ void conv_gemm_kernel(const float* __restrict__ memory,
                                 const float* __restrict__ W,
                                 const float* __restrict__ bias,
                                 float* __restrict__ out)
{
    __shared__ __align__(16) float As[TM][TK + 4];   // stride 36 floats = 144B (16B multiple)
    __shared__ __align__(16) float Ws[TK][TN + 4];   // stride 68 floats = 272B (16B multiple)
    __shared__ __align__(16) float Cs[TM][TN + 4];

    const int m0 = blockIdx.y * TM;
    const int n0 = blockIdx.x * TN;
    const int warp = threadIdx.x >> 5;       // 0..3
    const int wm = (warp >> 1) << 5;         // warp row offset: 0 or 32
    const int wn = (warp & 1) << 5;          // warp col offset: 0 or 32

    wmma::fragment<wmma::accumulator, 16, 16, 8, float> acc[2][2];
#pragma unroll
    for (int i = 0; i < 2; i++)
#pragma unroll
        for (int j = 0; j < 2; j++)
            wmma::fill_fragment(acc[i][j], 0.0f);

    for (int k0 = 0; k0 < 4096; k0 += TK) {
        // Load A tile: 64 rows x 32 k  (512 float4 / 128 threads = 4 each)
        for (int i = threadIdx.x; i < TM * (TK / 4); i += 128) {
            int row = i >> 3;
            int kq  = (i & 7) << 2;
            int m = m0 + row;
            const float* ap = memory + (size_t)(m >> 5) * 4194304u + 2097152u
                              + (size_t)(m & 31) * 4096u + (unsigned)(k0 + kq);
            float4 v = *(const float4*)ap;
            As[row][kq + 0] = wmma::__float_to_tf32(v.x);
            As[row][kq + 1] = wmma::__float_to_tf32(v.y);
            As[row][kq + 2] = wmma::__float_to_tf32(v.z);
            As[row][kq + 3] = wmma::__float_to_tf32(v.w);
        }
        // Load W tile: 32 k x 64 n  (512 float4 / 128 threads = 4 each)
        for (int i = threadIdx.x; i < TK * (TN / 4); i += 128) {
            int kr = i >> 4;
            int nq = (i & 15) << 2;
            float4 v = *(const float4*)(W + (size_t)(k0 + kr) * 1024u + (unsigned)(n0 + nq));
            Ws[kr][nq + 0] = wmma::__float_to_tf32(v.x);
            Ws[kr][nq + 1] = wmma::__float_to_tf32(v.y);
            Ws[kr][nq + 2] = wmma::__float_to_tf32(v.z);
            Ws[kr][nq + 3] = wmma::__float_to_tf32(v.w);
        }
        __syncthreads();

#pragma unroll
        for (int kk = 0; kk < TK; kk += 8) {
            wmma::fragment<wmma::matrix_a, 16, 16, 8, wmma::precision::tf32, wmma::row_major> a0, a1;
            wmma::fragment<wmma::matrix_b, 16, 16, 8, wmma::precision::tf32, wmma::row_major> b0, b1;
            wmma::load_matrix_sync(a0, &As[wm][kk],      TK + 4);
            wmma::load_matrix_sync(a1, &As[wm + 16][kk], TK + 4);
            wmma::load_matrix_sync(b0, &Ws[kk][wn],      TN + 4);
            wmma::load_matrix_sync(b1, &Ws[kk][wn + 16], TN + 4);
            wmma::mma_sync(acc[0][0], a0, b0, acc[0][0]);
            wmma::mma_sync(acc[0][1], a0, b1, acc[0][1]);
            wmma::mma_sync(acc[1][0], a1, b0, acc[1][0]);
            wmma::mma_sync(acc[1][1], a1, b1, acc[1][1]);
        }
        __syncthreads();
    }

    // Epilogue: stage to shared, add bias, scatter to output compression band.
#pragma unroll
    for (int i = 0; i < 2; i++)
#pragma unroll
        for (int j = 0; j < 2; j++)
            wmma::store_matrix_sync(&Cs[wm + 16 * i][wn + 16 * j], acc[i][j],
                                    TN + 4, wmma::mem_row_major);
    __syncthreads();

    for (int i = threadIdx.x; i < TM * (TN / 4); i += 128) {
        int row = i >> 4;
        int nq  = (i & 15) << 2;
        int m = m0 + row;
        int n = n0 + nq;
        float4 v  = *(const float4*)&Cs[row][nq];
        float4 bb = *(const float4*)(bias + n);
        v.x += bb.x; v.y += bb.y; v.z += bb.z; v.w += bb.w;
        float* op = out + (size_t)(m >> 5) * 4194304u
                        + (size_t)(2016u + (unsigned)(m & 31)) * 1024u + (unsigned)n;
        *(float4*)op = v;
    }
}

// ---------------------------------------------------------------------------
// Launch
// ---------------------------------------------------------------------------
extern "C" void kernel_launch(void* const* d_in, const int* in_sizes, int n_in,
                              void* d_out, int out_size)
{
    const float* inputs = (const float*)d_in[0];   // (32, 128, 1024)
    const float* memory = (const float*)d_in[1];   // (32, 4096, 1024)
    const float* conv_w = (const float*)d_in[2];   // (4, 1024, 1024)
    const float* conv_b = (const float*)d_in[3];   // (1024,)
    float* out = (float*)d_out;                    // (32, 4096, 1024)

    conv_gemm_kernel<<<dim3(16, 16), 128>>>(memory, conv_w, conv_b, out);
    copy_kernel<<<8192, 256>>>((const float4*)inputs, (const float4*)memory,
                               (float4*)out);
}

// round 4
// speedup vs baseline: 2.9991x; 2.9991x over previous
#include <cuda_runtime.h>
#include <cuda_bf16.h>
#include <cstdint>

// ===========================================================================
// Problem: B=32, T=128, F=1024, CONV_UNITS=2048, SHORT_UNITS=2048, RATE=4
//   out[b, 0:2016,    :] = memory[b, 32:2048,   :]
//   out[b, 2016:2048, :] = compression (GEMM)
//   out[b, 2048:3968, :] = memory[b, 2176:4096, :]
//   out[b, 3968:4096, :] = inputs[b, :, :]
// GEMM: C(1024x1024) = A(1024x4096) @ W(4096x1024) + bias
//   A row m=(b*32+t): 4096 contiguous floats at memory + b*2^22 + 2097152 + t*4096
//   W = conv_w viewed as (4096,1024) row-major (k-major rows, n contiguous).
// ===========================================================================

#define CP_ASYNC16(dst, src) \
    asm volatile("cp.async.cg.shared.global [%0], [%1], 16;" \
                 :: "r"(dst), "l"(src) : "memory")
#define CP_ASYNC_COMMIT() asm volatile("cp.async.commit_group;" ::: "memory")
#define CP_ASYNC_WAIT1()  asm volatile("cp.async.wait_group 1;" ::: "memory")
#define CP_ASYNC_WAIT0()  asm volatile("cp.async.wait_group 0;" ::: "memory")

__device__ __forceinline__ uint32_t smem_u32(const void* p) {
    uint32_t a;
    asm("{ .reg .u64 t; cvta.to.shared.u64 t, %1; cvt.u32.u64 %0, t; }"
        : "=r"(a) : "l"(p));
    return a;
}

__device__ __forceinline__ void mma_tf32_16n8k8(float* c, const uint32_t* a,
                                                const uint32_t* b) {
    asm volatile(
        "mma.sync.aligned.m16n8k8.row.col.f32.tf32.tf32.f32 "
        "{%0,%1,%2,%3}, {%4,%5,%6,%7}, {%8,%9}, {%0,%1,%2,%3};"
        : "+f"(c[0]), "+f"(c[1]), "+f"(c[2]), "+f"(c[3])
        : "r"(a[0]), "r"(a[1]), "r"(a[2]), "r"(a[3]),
          "r"(b[0]), "r"(b[1]));
}

// ---------------------------------------------------------------------------
// Pipelined tf32 GEMM.
// CTA tile 64(M) x 128(N), K-chunk 32, 3-stage cp.async pipeline.
// Grid (8, 16) = 128 CTAs. 256 threads, 8 warps: wm=(w&1)*32, wn=(w>>1)*32.
// Smem per stage: A 64x36 f32 (9216B) + B 32x132 f32 (16896B) = 26112B.
//
// PTX m16n8k8 tf32 A-fragment layout (lane g=lid>>2, t=lid&3):
//   a0 = A[g][t]   a1 = A[g+8][t]   a2 = A[g][t+4]   a3 = A[g+8][t+4]
// B-fragment (col-major 8x8): b0 = B[t][g], b1 = B[t+4][g]
// C-fragment: c0,c1 = C[g][2t,2t+1]; c2,c3 = C[g+8][2t,2t+1]
// ---------------------------------------------------------------------------
#define A_STRIDE 36
#define B_STRIDE 132
#define STAGE_BYTES 26112
#define NSTAGE 3

__global__ void __launch_bounds__(256, 1)
gemm_tf32(const float* __restrict__ memory,
          const float* __restrict__ W,
          const float* __restrict__ bias,
          float* __restrict__ out)
{
    extern __shared__ __align__(16) char smem[];
    const int tid = threadIdx.x;
    const int wid = tid >> 5;
    const int lid = tid & 31;
    const int m0 = blockIdx.y * 64;
    const int n0 = blockIdx.x * 128;
    const int wm = (wid & 1) * 32;
    const int wn = (wid >> 1) * 32;

    float acc[2][4][4];
#pragma unroll
    for (int i = 0; i < 2; i++)
#pragma unroll
        for (int j = 0; j < 4; j++)
#pragma unroll
            for (int k = 0; k < 4; k++) acc[i][j][k] = 0.0f;

    // Per-thread cp.async source/dest assignments.
    // A tile: 64 rows x 8 float4 = 512 transfers -> 2 per thread.
    // B tile: 32 rows x 32 float4 = 1024 transfers -> 4 per thread.
    auto issue_stage = [&](int kc) {
        const int s = kc % NSTAGE;
        char* sa = smem + s * STAGE_BYTES;
        char* sb = sa + 9216;
        const int k0 = kc << 5;
#pragma unroll
        for (int rep = 0; rep < 2; rep++) {
            const int i = tid + rep * 256;
            const int r = i >> 3, q = i & 7;
            const int m = m0 + r;
            const float* src = memory + ((size_t)(m >> 5) << 22) + 2097152u
                               + ((size_t)(m & 31) << 12) + (unsigned)(k0 + (q << 2));
            CP_ASYNC16(smem_u32(sa + (r * A_STRIDE + q * 4) * 4), src);
        }
#pragma unroll
        for (int rep = 0; rep < 4; rep++) {
            const int i = tid + rep * 256;
            const int r = i >> 5, q = i & 31;
            const float* src = W + (size_t)(k0 + r) * 1024u + (unsigned)(n0 + (q << 2));
            CP_ASYNC16(smem_u32(sb + (r * B_STRIDE + q * 4) * 4), src);
        }
    };

    issue_stage(0); CP_ASYNC_COMMIT();
    issue_stage(1); CP_ASYNC_COMMIT();

    for (int kc = 0; kc < 128; ++kc) {
        CP_ASYNC_WAIT1();
        __syncthreads();

        if (kc + 2 < 128) issue_stage(kc + 2);
        CP_ASYNC_COMMIT();

        const int s = kc % NSTAGE;
        const float* sa = (const float*)(smem + s * STAGE_BYTES);
        const float* sb = (const float*)(smem + s * STAGE_BYTES + 9216);

#pragma unroll
        for (int ks = 0; ks < 4; ++ks) {
            const int k = ks << 3;
            uint32_t af[2][4], bf[4][2];
            const int arow = wm + (lid >> 2);
            const int acol = k + (lid & 3);
#pragma unroll
            for (int mt = 0; mt < 2; mt++) {
                const float* ap = sa + (arow + mt * 16) * A_STRIDE + acol;
                af[mt][0] = __float_as_uint(ap[0]);                  // A[g][t]
                af[mt][1] = __float_as_uint(ap[8 * A_STRIDE]);       // A[g+8][t]
                af[mt][2] = __float_as_uint(ap[4]);                  // A[g][t+4]
                af[mt][3] = __float_as_uint(ap[8 * A_STRIDE + 4]);   // A[g+8][t+4]
            }
            const int brow = k + (lid & 3);
            const int bcol = wn + (lid >> 2);
#pragma unroll
            for (int nt = 0; nt < 4; nt++) {
                const float* bp = sb + brow * B_STRIDE + bcol + nt * 8;
                bf[nt][0] = __float_as_uint(bp[0]);                  // B[t][g]
                bf[nt][1] = __float_as_uint(bp[4 * B_STRIDE]);       // B[t+4][g]
            }
#pragma unroll
            for (int mt = 0; mt < 2; mt++)
#pragma unroll
                for (int nt = 0; nt < 4; nt++)
                    mma_tf32_16n8k8(acc[mt][nt], af[mt], bf[nt]);
        }
        __syncthreads();
    }
    CP_ASYNC_WAIT0();

    // Epilogue: direct float2 stores into the compression band + bias.
#pragma unroll
    for (int mt = 0; mt < 2; mt++) {
#pragma unroll
        for (int nt = 0; nt < 4; nt++) {
            const int g = n0 + wn + nt * 8 + (lid & 3) * 2;
            const float2 bv = *(const float2*)(bias + g);
            const int m_lo = m0 + wm + mt * 16 + (lid >> 2);
            const int m_hi = m_lo + 8;
            float2 v0 = { acc[mt][nt][0] + bv.x, acc[mt][nt][1] + bv.y };
            float2 v1 = { acc[mt][nt][2] + bv.x, acc[mt][nt][3] + bv.y };
            *(float2*)(out + ((size_t)(m_lo >> 5) << 22)
                           + (size_t)(2016 + (m_lo & 31)) * 1024 + g) = v0;
            *(float2*)(out + ((size_t)(m_hi >> 5) << 22)
                           + (size_t)(2016 + (m_hi & 31)) * 1024 + g) = v1;
        }
    }
}

// ---------------------------------------------------------------------------
// Copy kernel: pure shifted memcpy, float4-vectorized, grid-stride.
// ---------------------------------------------------------------------------
__global__ void copy_kernel(const float4* __restrict__ inputs,
                            const float4* __restrict__ memory,
                            float4* __restrict__ out)
{
    const unsigned total = 32u * 4096u * 256u;
    const unsigned stride = gridDim.x * blockDim.x;
    for (unsigned v = blockIdx.x * blockDim.x + threadIdx.x; v < total; v += stride) {
        unsigned f4 = v & 255u;
        unsigned rg = v >> 8;
        unsigned b  = rg >> 12;
        unsigned r  = rg & 4095u;
        float4 val;
        if (r < 2016u) {
            val = memory[(b << 20) + ((r + 32u) << 8) + f4];
        } else if (r < 2048u) {
            continue;  // compression band written by GEMM kernel
        } else if (r < 3968u) {
            val = memory[(b << 20) + ((r + 128u) << 8) + f4];
        } else {
            val = inputs[(b << 15) + ((r - 3968u) << 8) + f4];
        }
        out[v] = val;
    }
}

// ---------------------------------------------------------------------------
// Launch
// ---------------------------------------------------------------------------
extern "C" void kernel_launch(void* const* d_in, const int* in_sizes, int n_in,
                              void* d_out, int out_size)
{
    const float* inputs = (const float*)d_in[0];   // (32, 128, 1024)
    const float* memory = (const float*)d_in[1];   // (32, 4096, 1024)
    const float* conv_w = (const float*)d_in[2];   // (4, 1024, 1024)
    const float* conv_b = (const float*)d_in[3];   // (1024,)
    float* out = (float*)d_out;                    // (32, 4096, 1024)

    cudaFuncSetAttribute(gemm_tf32,
                         cudaFuncAttributeMaxDynamicSharedMemorySize,
                         STAGE_BYTES * NSTAGE);

    gemm_tf32<<<dim3(8, 16), 256, STAGE_BYTES * NSTAGE>>>(memory, conv_w,
                                                          conv_b, out);
    copy_kernel<<<8192, 256>>>((const float4*)inputs, (const float4*)memory,
                               (float4*)out);
}